// round 15
// baseline (speedup 1.0000x reference)
#include <cuda_runtime.h>

// SinusoidalEmbedding: out[b][s][d] = emb_table[x[b][s]][d] + PE[s][d]
// PE[s][2i] = sin(s*f_i), PE[s][2i+1] = cos(s*f_i), f_i = 10000^(-2i/1024)
//
// R12: kernel body = exact R7 winner (2 positions/CTA, 256 thr, plain v8
// loads/stores, default policy — all opcode-level hints proven neutral or
// harmful). SINGLE change: launch via cudaLaunchKernelEx with an L2
// AccessPolicyWindow (hitProp=Persisting) over the embedding table, so the
// ~96MB unique-row working set is held in the 126MB L2 across graph replays
// instead of being swept by the 128MB/replay write stream. No
// cudaDeviceSetLimit (would trip the device-limits guard); if the persisting
// carveout defaults to 0 this is a no-op and we learn the lever is closed.

#define BQ      8
#define S_LEN   4096
#define D_M     1024
#define TPB     256
#define POS_PER_CTA 2
#define VOCAB   50257

__device__ __forceinline__ void ldg_v8(const float* p, float* v) {
    unsigned r0, r1, r2, r3, r4, r5, r6, r7;
    asm volatile("ld.global.nc.v8.b32 {%0,%1,%2,%3,%4,%5,%6,%7}, [%8];"
                 : "=r"(r0), "=r"(r1), "=r"(r2), "=r"(r3),
                   "=r"(r4), "=r"(r5), "=r"(r6), "=r"(r7)
                 : "l"(p));
    v[0] = __uint_as_float(r0); v[1] = __uint_as_float(r1);
    v[2] = __uint_as_float(r2); v[3] = __uint_as_float(r3);
    v[4] = __uint_as_float(r4); v[5] = __uint_as_float(r5);
    v[6] = __uint_as_float(r6); v[7] = __uint_as_float(r7);
}

__device__ __forceinline__ void stg_v8(float* p, const float* v) {
    asm volatile("st.global.v8.b32 [%0], {%1,%2,%3,%4,%5,%6,%7,%8};"
                 :: "l"(p),
                    "r"(__float_as_uint(v[0])), "r"(__float_as_uint(v[1])),
                    "r"(__float_as_uint(v[2])), "r"(__float_as_uint(v[3])),
                    "r"(__float_as_uint(v[4])), "r"(__float_as_uint(v[5])),
                    "r"(__float_as_uint(v[6])), "r"(__float_as_uint(v[7]))
                 : "memory");
}

__global__ __launch_bounds__(TPB)
void sinemb_kernel(const void* __restrict__ xraw,
                   const float* __restrict__ emb,
                   float* __restrict__ out)
{
    const int t    = threadIdx.x;
    const int lane = t & 127;                        // owns floats 8*lane..+7
    const int s    = blockIdx.x * POS_PER_CTA + (t >> 7);  // position

    // ---- index dtype detect (int64 vs int32) ----
    const unsigned int* w = (const unsigned int*)xraw;
    const bool is64 = ((w[1] | w[3] | w[5] | w[7]) == 0u);

    // ---- gather rows for this position across the batch ----
    int rows[BQ];
    if (is64) {
        const long long* x64 = (const long long*)xraw;
        #pragma unroll
        for (int b = 0; b < BQ; b++) rows[b] = (int)x64[(long long)b * S_LEN + s];
    } else {
        const int* x32 = (const int*)xraw;
        #pragma unroll
        for (int b = 0; b < BQ; b++) rows[b] = x32[b * S_LEN + s];
    }

    // ---- PE: 4 (sin,cos) pairs for this thread's 8 floats ----
    const float c_exp = -0.02595256324130752f;   // -2*log2(10000)/1024
    const float fs = (float)s;
    float p[8];
    #pragma unroll
    for (int i = 0; i < 4; i++) {
        float f = exp2f(c_exp * (float)(4 * lane + i));
        sincosf(fs * f, &p[2 * i], &p[2 * i + 1]);
    }

    // ---- gather + add + store, 256-bit accesses, default policy ----
    #pragma unroll
    for (int b = 0; b < BQ; b++) {
        float e[8];
        ldg_v8(emb + (long long)rows[b] * D_M + 8 * lane, e);
        float o[8];
        #pragma unroll
        for (int i = 0; i < 8; i++) o[i] = e[i] + p[i];
        stg_v8(out + ((long long)b * S_LEN + s) * D_M + 8 * lane, o);
    }
}

extern "C" void kernel_launch(void* const* d_in, const int* in_sizes, int n_in,
                              void* d_out, int out_size)
{
    const void*  x   = d_in[0];                 // [8, 4096] int64 (or int32)
    const float* emb = (const float*)d_in[1];   // [50257, 1024] fp32
    float*       out = (float*)d_out;           // [8, 4096, 1024] fp32

    // L2 persistence window over the embedding table (launch attribute;
    // recorded into the captured graph node; no device-limit changes).
    int dev = 0;
    cudaGetDevice(&dev);
    int max_win = 0;
    cudaDeviceGetAttribute(&max_win, cudaDevAttrMaxAccessPolicyWindowSize, dev);

    size_t table_bytes = (size_t)VOCAB * D_M * sizeof(float);   // ~196 MB
    size_t win_bytes   = table_bytes;
    if (max_win > 0 && (size_t)max_win < win_bytes) win_bytes = (size_t)max_win;

    cudaLaunchConfig_t cfg = {};
    cfg.gridDim  = dim3(S_LEN / POS_PER_CTA);
    cfg.blockDim = dim3(TPB);
    cfg.dynamicSmemBytes = 0;

    cudaLaunchAttribute attr[1];
    attr[0].id = cudaLaunchAttributeAccessPolicyWindow;
    attr[0].val.accessPolicyWindow.base_ptr  = (void*)emb;
    attr[0].val.accessPolicyWindow.num_bytes = win_bytes;
    attr[0].val.accessPolicyWindow.hitRatio  = 0.6f;
    attr[0].val.accessPolicyWindow.hitProp   = cudaAccessPropertyPersisting;
    attr[0].val.accessPolicyWindow.missProp  = cudaAccessPropertyNormal;
    cfg.attrs    = attr;
    cfg.numAttrs = 1;

    cudaError_t err = cudaLaunchKernelEx(&cfg, sinemb_kernel, x, emb, out);
    if (err != cudaSuccess) {
        // Fallback: plain launch (identical kernel) if attribute unsupported.
        sinemb_kernel<<<S_LEN / POS_PER_CTA, TPB>>>(x, emb, out);
    }
}

// round 16
// speedup vs baseline: 1.0227x; 1.0227x over previous
#include <cuda_runtime.h>

// SinusoidalEmbedding: out[b][s][d] = emb_table[x[b][s]][d] + PE[s][d]
// PE[s][2i] = sin(s*f_i), PE[s][2i+1] = cos(s*f_i), f_i = 10000^(-2i/1024)
//
// FINAL (lock-in of the measured optimum, = R2):
//   grid 4096 (one CTA per position s), 256 threads (one float4 of D each),
//   no shared memory, no barriers, no cache-policy hints, plain launch.
// Evidence across 6 profiled variants: occupancy (60-83%), per-thread MLP
// (1-8), access width (128/256-bit), .cs stores, evict_last loads, and an
// L2 access-policy window ALL land on or below the 36.0us / 68% DRAM
// plateau — this mixed random-gather + streaming-write pattern is at its
// DRAM-efficiency ceiling (~5.3 TB/s) and this shape measured fastest.

#define D_M4    256      // D_M/4
#define BQ      8
#define S_LEN   4096

__global__ __launch_bounds__(256)
void sinemb_kernel(const void* __restrict__ xraw,
                   const float* __restrict__ emb,
                   float* __restrict__ out)
{
    const int t = threadIdx.x;          // float4 index within D: d = 4t..4t+3
    const int s = blockIdx.x;           // position

    // ---- index dtype detect (int64 vs int32), uniform broadcast loads ----
    // int64 LE with values < 50257 => all high words zero; for int32 the odd
    // words are independent random indices, P(4 zeros) ~ (2e-5)^4 ~ 0.
    const unsigned int* w = (const unsigned int*)xraw;
    const bool is64 = ((w[1] | w[3] | w[5] | w[7]) == 0u);

    // ---- gather rows for this position across the batch (uniform per CTA) ----
    int rows[BQ];
    if (is64) {
        const long long* x64 = (const long long*)xraw;
        #pragma unroll
        for (int b = 0; b < BQ; b++) rows[b] = (int)x64[(long long)b * S_LEN + s];
    } else {
        const int* x32 = (const int*)xraw;
        #pragma unroll
        for (int b = 0; b < BQ; b++) rows[b] = x32[b * S_LEN + s];
    }

    // ---- positional encoding for this thread's float4 ----
    // f_i = 2^(c_exp * i), c_exp = -2*log2(10000)/1024
    const float c_exp = -0.02595256324130752f;
    const float fs = (float)s;
    float f0 = exp2f(c_exp * (float)(2 * t));
    float f1 = exp2f(c_exp * (float)(2 * t + 1));
    float4 p;
    sincosf(fs * f0, &p.x, &p.y);
    sincosf(fs * f1, &p.z, &p.w);

    // ---- 8 gather + add + store (coalesced float4, default policy) ----
    const float4* emb4 = (const float4*)emb;
    float4*       out4 = (float4*)out;
    #pragma unroll
    for (int b = 0; b < BQ; b++) {
        float4 e = __ldg(&emb4[(long long)rows[b] * D_M4 + t]);
        float4 o;
        o.x = e.x + p.x; o.y = e.y + p.y;
        o.z = e.z + p.z; o.w = e.w + p.w;
        out4[((long long)b * S_LEN + s) * D_M4 + t] = o;
    }
}

extern "C" void kernel_launch(void* const* d_in, const int* in_sizes, int n_in,
                              void* d_out, int out_size)
{
    const void*  x   = d_in[0];                 // [8, 4096] int64 (or int32)
    const float* emb = (const float*)d_in[1];   // [50257, 1024] fp32
    float*       out = (float*)d_out;           // [8, 4096, 1024] fp32

    sinemb_kernel<<<S_LEN, 256>>>(x, emb, out);
}

// round 17
// speedup vs baseline: 1.0287x; 1.0059x over previous
#include <cuda_runtime.h>

// SinusoidalEmbedding: out[b][s][d] = emb_table[x[b][s]][d] + PE[s][d]
// PE[s][2i] = sin(s*f_i), PE[s][2i+1] = cos(s*f_i), f_i = 10000^(-2i/1024)
//
// FINAL — locked optimum (R2 configuration).
//   grid 4096 (one CTA per position s), 256 threads (one float4 of D each),
//   no shared memory, no barriers, no cache-policy hints, plain launch.
//
// Evidence (7 profiled variants): occupancy 60-84%, per-thread MLP 1-8,
// 128/256-bit accesses, .cs stores, evict_last loads, and an L2
// access-policy window all land on or below the ~36-37us / ~67% DRAM
// plateau. Traffic is near-compulsory (134MB writes + ~61MB reads after
// cross-replay L2 retention); the pattern is capped at ~5.3 TB/s effective
// HBM throughput by the mixed random-gather/streaming-write access mix.
// This shape measured fastest (36.0us kernel) at the lowest register count.

#define D_M4    256      // D_M/4
#define BQ      8
#define S_LEN   4096

__global__ __launch_bounds__(256)
void sinemb_kernel(const void* __restrict__ xraw,
                   const float* __restrict__ emb,
                   float* __restrict__ out)
{
    const int t = threadIdx.x;          // float4 index within D: d = 4t..4t+3
    const int s = blockIdx.x;           // position

    // ---- index dtype detect (int64 vs int32), uniform broadcast loads ----
    // int64 LE with values < 50257 => all high words zero; for int32 the odd
    // words are independent random indices, P(4 zeros) ~ (2e-5)^4 ~ 0.
    const unsigned int* w = (const unsigned int*)xraw;
    const bool is64 = ((w[1] | w[3] | w[5] | w[7]) == 0u);

    // ---- gather rows for this position across the batch (uniform per CTA) ----
    int rows[BQ];
    if (is64) {
        const long long* x64 = (const long long*)xraw;
        #pragma unroll
        for (int b = 0; b < BQ; b++) rows[b] = (int)x64[(long long)b * S_LEN + s];
    } else {
        const int* x32 = (const int*)xraw;
        #pragma unroll
        for (int b = 0; b < BQ; b++) rows[b] = x32[b * S_LEN + s];
    }

    // ---- positional encoding for this thread's float4 ----
    // f_i = 2^(c_exp * i), c_exp = -2*log2(10000)/1024
    const float c_exp = -0.02595256324130752f;
    const float fs = (float)s;
    float f0 = exp2f(c_exp * (float)(2 * t));
    float f1 = exp2f(c_exp * (float)(2 * t + 1));
    float4 p;
    sincosf(fs * f0, &p.x, &p.y);
    sincosf(fs * f1, &p.z, &p.w);

    // ---- 8 gather + add + store (coalesced float4, default policy) ----
    const float4* emb4 = (const float4*)emb;
    float4*       out4 = (float4*)out;
    #pragma unroll
    for (int b = 0; b < BQ; b++) {
        float4 e = __ldg(&emb4[(long long)rows[b] * D_M4 + t]);
        float4 o;
        o.x = e.x + p.x; o.y = e.y + p.y;
        o.z = e.z + p.z; o.w = e.w + p.w;
        out4[((long long)b * S_LEN + s) * D_M4 + t] = o;
    }
}

extern "C" void kernel_launch(void* const* d_in, const int* in_sizes, int n_in,
                              void* d_out, int out_size)
{
    const void*  x   = d_in[0];                 // [8, 4096] int64 (or int32)
    const float* emb = (const float*)d_in[1];   // [50257, 1024] fp32
    float*       out = (float*)d_out;           // [8, 4096, 1024] fp32

    sinemb_kernel<<<S_LEN, 256>>>(x, emb, out);
}